// round 4
// baseline (speedup 1.0000x reference)
#include <cuda_runtime.h>
#include <cuda_bf16.h>
#include <cstdint>

#define DIM   128
#define NP    8128
#define BATCH 262144
#define NG    8
#define GROUP (NP / NG)          // 1016
#define MCTA  256
#define MTILES (BATCH / MCTA)    // 1024

// ---------------- scratch (no cudaMalloc allowed) ----------------
__device__ float  g_parts[NG * DIM * DIM];   // column-major partial products
__device__ uint4  g_bpack[8 * 16 * 32];      // [kstep][ntile][lane] -> {b0h,b1h,b0l,b1l}

// ---------------- helpers ----------------
__device__ __forceinline__ unsigned pk2(float a, float b) {
    __nv_bfloat162 t = __floats2bfloat162_rn(a, b);  // .x = a (low half)
    return *reinterpret_cast<unsigned*>(&t);
}

// hi = packed bf16(a),bf16(b); lo = packed residuals, hi floats recovered by bit ops
__device__ __forceinline__ void cvt2b(float2 v, unsigned& hi, unsigned& lo) {
    unsigned h = pk2(v.x, v.y);
    float hx = __uint_as_float(h << 16);
    float hy = __uint_as_float(h & 0xffff0000u);
    hi = h;
    lo = pk2(v.x - hx, v.y - hy);
}

__device__ __forceinline__ void mma16816(float* c, const unsigned* a, unsigned b0, unsigned b1) {
    asm("mma.sync.aligned.m16n8k16.row.col.f32.bf16.bf16.f32 "
        "{%0,%1,%2,%3}, {%4,%5,%6,%7}, {%8,%9}, {%0,%1,%2,%3};\n"
        : "+f"(c[0]), "+f"(c[1]), "+f"(c[2]), "+f"(c[3])
        : "r"(a[0]), "r"(a[1]), "r"(a[2]), "r"(a[3]), "r"(b0), "r"(b1));
}

// ---------------- phase 1a: 8 partial products of the rotation chain ----------------
__global__ __launch_bounds__(128) void partials_kernel(const float* __restrict__ angles) {
    __shared__ float2 cs[GROUP];
    extern __shared__ float ws[];   // column-major ws[c*DIM + r], 64KB
    int r = threadIdx.x, gI = blockIdx.x;

    for (int p = r; p < GROUP; p += 128) {
        float s, c;
        sincosf(angles[gI * GROUP + p], &s, &c);
        cs[p] = make_float2(c, s);
    }
    for (int c = 0; c < DIM; ++c) ws[c * DIM + r] = (c == r) ? 1.f : 0.f;
    __syncthreads();

    int p0 = gI * GROUP;
    int i = 0, rem = p0;
    while (rem >= DIM - 1 - i) { rem -= DIM - 1 - i; ++i; }
    int j = i + 1 + rem;

    float wi = ws[i * DIM + r];
    #pragma unroll 4
    for (int p = 0; p < GROUP; ++p) {
        float2 v = cs[p];
        float wj = ws[j * DIM + r];
        float nwi = wi * v.x + wj * v.y;
        ws[j * DIM + r] = wj * v.x - wi * v.y;
        wi = nwi;
        if (++j == DIM) {
            ws[i * DIM + r] = wi;
            ++i; j = i + 1;
            wi = ws[i * DIM + r];
        }
    }
    ws[i * DIM + r] = wi;
    __syncthreads();
    for (int idx = r; idx < DIM * DIM; idx += 128)
        g_parts[gI * DIM * DIM + idx] = ws[idx];
}

// ---------------- phase 1b: W columns via right-to-left chain; emit b-pack ----------------
// 16 CTAs x 256 threads. CTA bx owns W columns [8*bx, 8*bx+8).
// S <- P_m * S for m = 6..0, starting S = cols of P7. Then pack bf16 hi/lo fragments.
__global__ __launch_bounds__(256) void chain_kernel() {
    extern __shared__ float sm2[];
    float* P  = sm2;            // 16384 floats (full P_m)
    float* Sa = sm2 + 16384;    // 1024
    float* Sb = Sa + 1024;      // 1024

    int tid = threadIdx.x, r = tid & 127, h = tid >> 7;  // h in {0,1}
    int c0 = blockIdx.x * 8;

    for (int i = tid; i < 1024; i += 256)
        Sa[i] = g_parts[7 * DIM * DIM + c0 * DIM + i];

    float* S = Sa; float* S2 = Sb;
    for (int m = 6; m >= 0; --m) {
        float4* P4 = (float4*)P;
        const float4* G4 = (const float4*)(g_parts + m * DIM * DIM);
        #pragma unroll 4
        for (int i = tid; i < 4096; i += 256) P4[i] = G4[i];
        __syncthreads();

        float acc[4] = {0.f, 0.f, 0.f, 0.f};
        #pragma unroll 4
        for (int k = 0; k < DIM; k += 4) {
            float p0 = P[(k + 0) * DIM + r];
            float p1 = P[(k + 1) * DIM + r];
            float p2 = P[(k + 2) * DIM + r];
            float p3 = P[(k + 3) * DIM + r];
            #pragma unroll
            for (int cc = 0; cc < 4; ++cc) {
                float4 s4 = *(const float4*)&S[(h * 4 + cc) * DIM + k];
                acc[cc] = fmaf(p0, s4.x, acc[cc]);
                acc[cc] = fmaf(p1, s4.y, acc[cc]);
                acc[cc] = fmaf(p2, s4.z, acc[cc]);
                acc[cc] = fmaf(p3, s4.w, acc[cc]);
            }
        }
        __syncthreads();
        #pragma unroll
        for (int cc = 0; cc < 4; ++cc)
            S2[(h * 4 + cc) * DIM + r] = acc[cc];
        __syncthreads();
        float* tmp = S; S = S2; S2 = tmp;
    }

    // pack b-fragments: 256 threads = 8 ksteps x 32 lanes
    {
        int lane = tid & 31, s = tid >> 5;
        int g2 = lane >> 2, tg2 = lane & 3;
        int k0 = s * 16 + tg2 * 2;
        const float* Wc = S + g2 * DIM;             // column c0 + g2
        float w00 = Wc[k0], w01 = Wc[k0 + 1], w10 = Wc[k0 + 8], w11 = Wc[k0 + 9];
        uint4 bp;
        unsigned h0 = pk2(w00, w01);
        unsigned h1 = pk2(w10, w11);
        bp.x = h0;
        bp.y = h1;
        bp.z = pk2(w00 - __uint_as_float(h0 << 16), w01 - __uint_as_float(h0 & 0xffff0000u));
        bp.w = pk2(w10 - __uint_as_float(h1 << 16), w11 - __uint_as_float(h1 & 0xffff0000u));
        g_bpack[s * 512 + blockIdx.x * 32 + lane] = bp;
    }
}

// ---------------- phase 2: GEMM  out = x @ W + bias  (3x bf16 split mma) ----------------
// 512 threads/CTA (16 warps, 4/SMSP), warp owns 16 rows; A straight gmem->regs,
// depth-2 prefetch; no in-loop barriers.
__global__ __launch_bounds__(512, 1) void gemm_kernel(const float* __restrict__ x,
                                                      const float* __restrict__ bias,
                                                      float* __restrict__ out) {
    extern __shared__ char smraw[];
    uint4* Bp = (uint4*)smraw;               // 4096 uint4 = 64KB
    float* bs = (float*)(Bp + 4096);         // 128 floats

    int tid = threadIdx.x, lane = tid & 31, w = tid >> 5;
    int g = lane >> 2, tg = lane & 3;

    for (int idx = tid; idx < 4096; idx += 512) Bp[idx] = g_bpack[idx];
    if (tid < DIM) bs[tid] = bias[tid];

    const float* xw = x + ((size_t)blockIdx.x * MCTA + w * 16) * DIM;

    float2 P[2][4];
#define FETCH(B, S) { int kk = (S) * 16 + 2 * tg;                    \
    P[B][0] = *(const float2*)(xw + (g    ) * DIM + kk);             \
    P[B][1] = *(const float2*)(xw + (g + 8) * DIM + kk);             \
    P[B][2] = *(const float2*)(xw + (g    ) * DIM + kk + 8);         \
    P[B][3] = *(const float2*)(xw + (g + 8) * DIM + kk + 8); }

    FETCH(0, 0);
    FETCH(1, 1);
    __syncthreads();   // B-pack + bias ready

    float acc[16][4];
    #pragma unroll
    for (int t = 0; t < 16; ++t)
        #pragma unroll
        for (int q = 0; q < 4; ++q) acc[t][q] = 0.f;

    #pragma unroll
    for (int s = 0; s < 8; ++s) {
        int b = s & 1;
        unsigned ah[4], al[4];
        cvt2b(P[b][0], ah[0], al[0]);
        cvt2b(P[b][1], ah[1], al[1]);
        cvt2b(P[b][2], ah[2], al[2]);
        cvt2b(P[b][3], ah[3], al[3]);
        if (s < 6) FETCH(b, s + 2);
        const uint4* Bq = Bp + s * 512 + lane;
        #pragma unroll
        for (int t = 0; t < 16; ++t) {
            uint4 bb = Bq[t * 32];
            mma16816(acc[t], ah, bb.x, bb.y);   // hi*hi
            mma16816(acc[t], al, bb.x, bb.y);   // lo*hi
            mma16816(acc[t], ah, bb.z, bb.w);   // hi*lo
        }
    }
#undef FETCH

    float* outw = out + ((size_t)blockIdx.x * MCTA + w * 16) * DIM;
    #pragma unroll
    for (int t = 0; t < 16; ++t) {
        int col = t * 8 + tg * 2;
        float b0 = bs[col], b1 = bs[col + 1];
        *(float2*)(outw + (g    ) * DIM + col) = make_float2(acc[t][0] + b0, acc[t][1] + b1);
        *(float2*)(outw + (g + 8) * DIM + col) = make_float2(acc[t][2] + b0, acc[t][3] + b1);
    }
}

// ---------------- launcher ----------------
extern "C" void kernel_launch(void* const* d_in, const int* in_sizes, int n_in,
                              void* d_out, int out_size) {
    const float* x      = (const float*)d_in[0];
    const float* angles = (const float*)d_in[1];
    const float* bias   = (const float*)d_in[2];
    float* out = (float*)d_out;

    const int PART_SMEM  = DIM * DIM * 4;              // 65536 dynamic
    const int CHAIN_SMEM = (16384 + 2048) * 4;         // 73728
    const int GEMM_SMEM  = 4096 * 16 + DIM * 4;        // 66048

    cudaFuncSetAttribute(partials_kernel, cudaFuncAttributeMaxDynamicSharedMemorySize, PART_SMEM);
    cudaFuncSetAttribute(chain_kernel,    cudaFuncAttributeMaxDynamicSharedMemorySize, CHAIN_SMEM);
    cudaFuncSetAttribute(gemm_kernel,     cudaFuncAttributeMaxDynamicSharedMemorySize, GEMM_SMEM);

    partials_kernel<<<NG, 128, PART_SMEM>>>(angles);
    chain_kernel<<<16, 256, CHAIN_SMEM>>>();
    gemm_kernel<<<MTILES, 512, GEMM_SMEM>>>(x, bias, out);
}

// round 5
// speedup vs baseline: 1.0952x; 1.0952x over previous
#include <cuda_runtime.h>
#include <cuda_bf16.h>
#include <cstdint>

#define DIM   128
#define NP    8128
#define BATCH 262144
#define NG    8
#define GROUP (NP / NG)          // 1016
#define MCTA  256
#define MTILES (BATCH / MCTA)    // 1024

// ---------------- scratch (no cudaMalloc allowed) ----------------
__device__ float  g_parts[NG * DIM * DIM];   // column-major partial products
__device__ uint4  g_bpack[8 * 16 * 32];      // [kstep][ntile][lane] -> {Eh0,Eh1,El0,El1}

// ---------------- helpers ----------------
__device__ __forceinline__ unsigned pk2(float a, float b) {
    __nv_bfloat162 t = __floats2bfloat162_rn(a, b);  // .x = a (low half)
    return *reinterpret_cast<unsigned*>(&t);
}

__device__ __forceinline__ void mma16816(float* c, const unsigned* a, unsigned b0, unsigned b1) {
    asm("mma.sync.aligned.m16n8k16.row.col.f32.bf16.bf16.f32 "
        "{%0,%1,%2,%3}, {%4,%5,%6,%7}, {%8,%9}, {%0,%1,%2,%3};\n"
        : "+f"(c[0]), "+f"(c[1]), "+f"(c[2]), "+f"(c[3])
        : "r"(a[0]), "r"(a[1]), "r"(a[2]), "r"(a[3]), "r"(b0), "r"(b1));
}

// ---------------- phase 1a: 8 partial products, software-pipelined chain ----------------
__global__ __launch_bounds__(128) void partials_kernel(const float* __restrict__ angles) {
    __shared__ float2 cs[GROUP];
    extern __shared__ float ws[];   // column-major ws[c*DIM + r], 64KB
    int r = threadIdx.x, gI = blockIdx.x;

    for (int p = r; p < GROUP; p += 128) {
        float s, c;
        sincosf(angles[gI * GROUP + p], &s, &c);
        cs[p] = make_float2(c, s);
    }
    for (int c = 0; c < DIM; ++c) ws[c * DIM + r] = (c == r) ? 1.f : 0.f;
    __syncthreads();

    // locate start pair (i, j0) for this group
    int p0 = gI * GROUP;
    int i = 0, rem = p0;
    while (rem >= DIM - 1 - i) { rem -= DIM - 1 - i; ++i; }
    int j0 = i + 1 + rem;

    int p = 0;
    while (p < GROUP) {
        float wi = ws[i * DIM + r];
        int navail = GROUP - p;
        int jend = DIM;
        if (jend - j0 > navail) jend = j0 + navail;
        int j = j0;

        if (jend - j > 4) {
            // depth-4 register-ring pipeline (branch-free inner loop)
            float f0 = ws[(j + 0) * DIM + r];
            float f1 = ws[(j + 1) * DIM + r];
            float f2 = ws[(j + 2) * DIM + r];
            float f3 = ws[(j + 3) * DIM + r];
            float2 v0 = cs[p + 0], v1 = cs[p + 1], v2 = cs[p + 2], v3 = cs[p + 3];
            #pragma unroll 4
            for (; j < jend - 4; ++j, ++p) {
                float wj = f0; float2 v = v0;
                f0 = f1; f1 = f2; f2 = f3; f3 = ws[(j + 4) * DIM + r];
                v0 = v1; v1 = v2; v2 = v3; v3 = cs[p + 4];
                float nwj = fmaf(wj, v.x, -(wi * v.y));
                wi = fmaf(wi, v.x, wj * v.y);
                ws[j * DIM + r] = nwj;
            }
        }
        for (; j < jend; ++j, ++p) {
            float2 v = cs[p];
            float wj = ws[j * DIM + r];
            float nwj = fmaf(wj, v.x, -(wi * v.y));
            wi = fmaf(wi, v.x, wj * v.y);
            ws[j * DIM + r] = nwj;
        }
        ws[i * DIM + r] = wi;
        ++i; j0 = i + 1;
    }
    __syncthreads();
    for (int idx = r; idx < DIM * DIM; idx += 128)
        g_parts[gI * DIM * DIM + idx] = ws[idx];
}

// ---------------- phase 1b: W cols via right-to-left chain; emit E = W - I b-pack ----------------
__global__ __launch_bounds__(256) void chain_kernel() {
    extern __shared__ float sm2[];
    float* P  = sm2;            // 16384 floats (full P_m)
    float* Sa = sm2 + 16384;    // 1024
    float* Sb = Sa + 1024;      // 1024

    int tid = threadIdx.x, r = tid & 127, h = tid >> 7;  // h in {0,1}
    int c0 = blockIdx.x * 8;

    for (int i = tid; i < 1024; i += 256)
        Sa[i] = g_parts[7 * DIM * DIM + c0 * DIM + i];

    float* S = Sa; float* S2 = Sb;
    for (int m = 6; m >= 0; --m) {
        float4* P4 = (float4*)P;
        const float4* G4 = (const float4*)(g_parts + m * DIM * DIM);
        #pragma unroll 4
        for (int i = tid; i < 4096; i += 256) P4[i] = G4[i];
        __syncthreads();

        float acc[4] = {0.f, 0.f, 0.f, 0.f};
        #pragma unroll 4
        for (int k = 0; k < DIM; k += 4) {
            float p0 = P[(k + 0) * DIM + r];
            float p1 = P[(k + 1) * DIM + r];
            float p2 = P[(k + 2) * DIM + r];
            float p3 = P[(k + 3) * DIM + r];
            #pragma unroll
            for (int cc = 0; cc < 4; ++cc) {
                float4 s4 = *(const float4*)&S[(h * 4 + cc) * DIM + k];
                acc[cc] = fmaf(p0, s4.x, acc[cc]);
                acc[cc] = fmaf(p1, s4.y, acc[cc]);
                acc[cc] = fmaf(p2, s4.z, acc[cc]);
                acc[cc] = fmaf(p3, s4.w, acc[cc]);
            }
        }
        __syncthreads();
        #pragma unroll
        for (int cc = 0; cc < 4; ++cc)
            S2[(h * 4 + cc) * DIM + r] = acc[cc];
        __syncthreads();
        float* tmp = S; S = S2; S2 = tmp;
    }

    // pack E-fragments: 256 threads = 8 ksteps x 32 lanes
    {
        int lane = tid & 31, s = tid >> 5;
        int g2 = lane >> 2, tg2 = lane & 3;
        int k0 = s * 16 + tg2 * 2;
        int n  = c0 + g2;
        const float* Wc = S + g2 * DIM;
        float w00 = Wc[k0]     - ((k0     == n) ? 1.f : 0.f);
        float w01 = Wc[k0 + 1] - ((k0 + 1 == n) ? 1.f : 0.f);
        float w10 = Wc[k0 + 8] - ((k0 + 8 == n) ? 1.f : 0.f);
        float w11 = Wc[k0 + 9] - ((k0 + 9 == n) ? 1.f : 0.f);
        uint4 bp;
        unsigned h0 = pk2(w00, w01);
        unsigned h1 = pk2(w10, w11);
        bp.x = h0;
        bp.y = h1;
        bp.z = pk2(w00 - __uint_as_float(h0 << 16), w01 - __uint_as_float(h0 & 0xffff0000u));
        bp.w = pk2(w10 - __uint_as_float(h1 << 16), w11 - __uint_as_float(h1 & 0xffff0000u));
        g_bpack[s * 512 + blockIdx.x * 32 + lane] = bp;
    }
}

// ---------------- phase 2: GEMM  out = x + x_h @ (E_h + E_l) + bias ----------------
// 512 threads/CTA (16 warps), warp owns 16 rows; A straight gmem->regs with depth-2
// prefetch; identity added from the fp32 A fragments (lane's k-set == lane's C-col set).
__global__ __launch_bounds__(512, 1) void gemm_kernel(const float* __restrict__ x,
                                                      const float* __restrict__ bias,
                                                      float* __restrict__ out) {
    extern __shared__ char smraw[];
    uint4* Bp = (uint4*)smraw;               // 4096 uint4 = 64KB
    float* bs = (float*)(Bp + 4096);         // 128 floats

    int tid = threadIdx.x, lane = tid & 31, w = tid >> 5;
    int g = lane >> 2, tg = lane & 3;

    for (int idx = tid; idx < 4096; idx += 512) Bp[idx] = g_bpack[idx];
    if (tid < DIM) bs[tid] = bias[tid];

    const float* xw = x + ((size_t)blockIdx.x * MCTA + w * 16) * DIM;

    float2 P[2][4];
#define FETCH(B, S) { int kk = (S) * 16 + 2 * tg;                    \
    P[B][0] = *(const float2*)(xw + (g    ) * DIM + kk);             \
    P[B][1] = *(const float2*)(xw + (g + 8) * DIM + kk);             \
    P[B][2] = *(const float2*)(xw + (g    ) * DIM + kk + 8);         \
    P[B][3] = *(const float2*)(xw + (g + 8) * DIM + kk + 8); }

    FETCH(0, 0);
    FETCH(1, 1);
    __syncthreads();   // B-pack + bias ready

    float acc[16][4];
    #pragma unroll
    for (int t = 0; t < 16; ++t)
        #pragma unroll
        for (int q = 0; q < 4; ++q) acc[t][q] = 0.f;

    #pragma unroll
    for (int s = 0; s < 8; ++s) {
        int b = s & 1;
        unsigned ah[4];
        ah[0] = pk2(P[b][0].x, P[b][0].y);
        ah[1] = pk2(P[b][1].x, P[b][1].y);
        ah[2] = pk2(P[b][2].x, P[b][2].y);
        ah[3] = pk2(P[b][3].x, P[b][3].y);
        // identity: add exact fp32 x into the matching C fragments
        acc[2*s][0]     += P[b][0].x;  acc[2*s][1]     += P[b][0].y;
        acc[2*s][2]     += P[b][1].x;  acc[2*s][3]     += P[b][1].y;
        acc[2*s + 1][0] += P[b][2].x;  acc[2*s + 1][1] += P[b][2].y;
        acc[2*s + 1][2] += P[b][3].x;  acc[2*s + 1][3] += P[b][3].y;
        if (s < 6) FETCH(b, s + 2);
        const uint4* Bq = Bp + s * 512 + lane;
        #pragma unroll
        for (int t = 0; t < 16; ++t) {
            uint4 bb = Bq[t * 32];
            mma16816(acc[t], ah, bb.x, bb.y);   // x_h * E_h
            mma16816(acc[t], ah, bb.z, bb.w);   // x_h * E_l
        }
    }
#undef FETCH

    float* outw = out + ((size_t)blockIdx.x * MCTA + w * 16) * DIM;
    #pragma unroll
    for (int t = 0; t < 16; ++t) {
        int col = t * 8 + tg * 2;
        float b0 = bs[col], b1 = bs[col + 1];
        *(float2*)(outw + (g    ) * DIM + col) = make_float2(acc[t][0] + b0, acc[t][1] + b1);
        *(float2*)(outw + (g + 8) * DIM + col) = make_float2(acc[t][2] + b0, acc[t][3] + b1);
    }
}

// ---------------- launcher ----------------
extern "C" void kernel_launch(void* const* d_in, const int* in_sizes, int n_in,
                              void* d_out, int out_size) {
    const float* x      = (const float*)d_in[0];
    const float* angles = (const float*)d_in[1];
    const float* bias   = (const float*)d_in[2];
    float* out = (float*)d_out;

    const int PART_SMEM  = DIM * DIM * 4;              // 65536 dynamic
    const int CHAIN_SMEM = (16384 + 2048) * 4;         // 73728
    const int GEMM_SMEM  = 4096 * 16 + DIM * 4;        // 66048

    cudaFuncSetAttribute(partials_kernel, cudaFuncAttributeMaxDynamicSharedMemorySize, PART_SMEM);
    cudaFuncSetAttribute(chain_kernel,    cudaFuncAttributeMaxDynamicSharedMemorySize, CHAIN_SMEM);
    cudaFuncSetAttribute(gemm_kernel,     cudaFuncAttributeMaxDynamicSharedMemorySize, GEMM_SMEM);

    partials_kernel<<<NG, 128, PART_SMEM>>>(angles);
    chain_kernel<<<16, 256, CHAIN_SMEM>>>();
    gemm_kernel<<<MTILES, 512, GEMM_SMEM>>>(x, bias, out);
}

// round 6
// speedup vs baseline: 1.1805x; 1.0779x over previous
#include <cuda_runtime.h>
#include <cuda_bf16.h>
#include <cuda_fp16.h>
#include <cstdint>

#define DIM   128
#define NP    8128
#define BATCH 262144
#define NG    8
#define GROUP (NP / NG)          // 1016
#define MCTA  256
#define MTILES (BATCH / MCTA)    // 1024

// ---------------- scratch (no cudaMalloc allowed) ----------------
__device__ float  g_parts[NG * DIM * DIM];   // column-major partial products
__device__ uint2  g_bpack[8 * 16 * 32];      // [kstep][ntile][lane] -> fp16 {E0,E1}

// ---------------- helpers ----------------
__device__ __forceinline__ unsigned pkh2(float a, float b) {
    __half2 t = __floats2half2_rn(a, b);     // .x = a (low half)
    return *reinterpret_cast<unsigned*>(&t);
}

__device__ __forceinline__ void mma16816h(float* c, const unsigned* a, unsigned b0, unsigned b1) {
    asm("mma.sync.aligned.m16n8k16.row.col.f32.f16.f16.f32 "
        "{%0,%1,%2,%3}, {%4,%5,%6,%7}, {%8,%9}, {%0,%1,%2,%3};\n"
        : "+f"(c[0]), "+f"(c[1]), "+f"(c[2]), "+f"(c[3])
        : "r"(a[0]), "r"(a[1]), "r"(a[2]), "r"(a[3]), "r"(b0), "r"(b1));
}

// ---------------- phase 1a: 8 partial products, depth-8 pipelined chain ----------------
__global__ __launch_bounds__(128) void partials_kernel(const float* __restrict__ angles) {
    __shared__ float2 cs[GROUP];
    extern __shared__ float ws[];   // column-major ws[c*DIM + r], 64KB
    int r = threadIdx.x, gI = blockIdx.x;

    for (int p = r; p < GROUP; p += 128) {
        float s, c;
        sincosf(angles[gI * GROUP + p], &s, &c);
        cs[p] = make_float2(c, s);
    }
    for (int c = 0; c < DIM; ++c) ws[c * DIM + r] = (c == r) ? 1.f : 0.f;
    __syncthreads();

    // locate start pair (i, j0) for this group
    int p0 = gI * GROUP;
    int i = 0, rem = p0;
    while (rem >= DIM - 1 - i) { rem -= DIM - 1 - i; ++i; }
    int j0 = i + 1 + rem;

    int p = 0;
    while (p < GROUP) {
        float wi = ws[i * DIM + r];
        int navail = GROUP - p;
        int jend = DIM;
        if (jend - j0 > navail) jend = j0 + navail;
        int j = j0;

        if (jend - j > 8) {
            // depth-8 register rings: 8-iter lookahead covers the 29-cyc LDS latency
            float  f[8];
            float2 v[8];
            #pragma unroll
            for (int q = 0; q < 8; ++q) { f[q] = ws[(j + q) * DIM + r]; v[q] = cs[p + q]; }
            #pragma unroll 8
            for (; j < jend - 8; ++j, ++p) {
                float wj = f[0]; float2 vv = v[0];
                #pragma unroll
                for (int q = 0; q < 7; ++q) { f[q] = f[q + 1]; v[q] = v[q + 1]; }
                f[7] = ws[(j + 8) * DIM + r];
                v[7] = cs[p + 8];
                float nwj = fmaf(wj, vv.x, -(wi * vv.y));
                wi = fmaf(wi, vv.x, wj * vv.y);
                ws[j * DIM + r] = nwj;
            }
        }
        for (; j < jend; ++j, ++p) {
            float2 vv = cs[p];
            float wj = ws[j * DIM + r];
            float nwj = fmaf(wj, vv.x, -(wi * vv.y));
            wi = fmaf(wi, vv.x, wj * vv.y);
            ws[j * DIM + r] = nwj;
        }
        ws[i * DIM + r] = wi;
        ++i; j0 = i + 1;
    }
    __syncthreads();
    for (int idx = r; idx < DIM * DIM; idx += 128)
        g_parts[gI * DIM * DIM + idx] = ws[idx];
}

// ---------------- phase 1b: W cols via right-to-left chain; emit E = W - I (fp16) ----------------
__global__ __launch_bounds__(256) void chain_kernel() {
    extern __shared__ float sm2[];
    float* P  = sm2;            // 16384 floats (full P_m)
    float* Sa = sm2 + 16384;    // 1024
    float* Sb = Sa + 1024;      // 1024

    int tid = threadIdx.x, r = tid & 127, h = tid >> 7;  // h in {0,1}
    int c0 = blockIdx.x * 8;

    for (int i = tid; i < 1024; i += 256)
        Sa[i] = g_parts[7 * DIM * DIM + c0 * DIM + i];

    float* S = Sa; float* S2 = Sb;
    for (int m = 6; m >= 0; --m) {
        float4* P4 = (float4*)P;
        const float4* G4 = (const float4*)(g_parts + m * DIM * DIM);
        #pragma unroll 4
        for (int i = tid; i < 4096; i += 256) P4[i] = G4[i];
        __syncthreads();

        float acc[4] = {0.f, 0.f, 0.f, 0.f};
        #pragma unroll 4
        for (int k = 0; k < DIM; k += 4) {
            float p0 = P[(k + 0) * DIM + r];
            float p1 = P[(k + 1) * DIM + r];
            float p2 = P[(k + 2) * DIM + r];
            float p3 = P[(k + 3) * DIM + r];
            #pragma unroll
            for (int cc = 0; cc < 4; ++cc) {
                float4 s4 = *(const float4*)&S[(h * 4 + cc) * DIM + k];
                acc[cc] = fmaf(p0, s4.x, acc[cc]);
                acc[cc] = fmaf(p1, s4.y, acc[cc]);
                acc[cc] = fmaf(p2, s4.z, acc[cc]);
                acc[cc] = fmaf(p3, s4.w, acc[cc]);
            }
        }
        __syncthreads();
        #pragma unroll
        for (int cc = 0; cc < 4; ++cc)
            S2[(h * 4 + cc) * DIM + r] = acc[cc];
        __syncthreads();
        float* tmp = S; S = S2; S2 = tmp;
    }

    // pack fp16 E-fragments: 256 threads = 8 ksteps x 32 lanes
    {
        int lane = tid & 31, s = tid >> 5;
        int g2 = lane >> 2, tg2 = lane & 3;
        int k0 = s * 16 + tg2 * 2;
        int n  = c0 + g2;
        const float* Wc = S + g2 * DIM;
        float w00 = Wc[k0]     - ((k0     == n) ? 1.f : 0.f);
        float w01 = Wc[k0 + 1] - ((k0 + 1 == n) ? 1.f : 0.f);
        float w10 = Wc[k0 + 8] - ((k0 + 8 == n) ? 1.f : 0.f);
        float w11 = Wc[k0 + 9] - ((k0 + 9 == n) ? 1.f : 0.f);
        uint2 bp;
        bp.x = pkh2(w00, w01);
        bp.y = pkh2(w10, w11);
        g_bpack[s * 512 + blockIdx.x * 32 + lane] = bp;
    }
}

// ---------------- phase 2: GEMM  out = x + x_h16 @ E_16 + bias ----------------
// 512 threads/CTA (16 warps), warp owns 16 rows; A straight gmem->regs with depth-2
// prefetch; identity added exactly from the fp32 A fragments; ONE fp16 mma per (s,t).
__global__ __launch_bounds__(512, 1) void gemm_kernel(const float* __restrict__ x,
                                                      const float* __restrict__ bias,
                                                      float* __restrict__ out) {
    extern __shared__ char smraw[];
    uint2* Bp = (uint2*)smraw;               // 4096 uint2 = 32KB
    float* bs = (float*)(Bp + 4096);         // 128 floats

    int tid = threadIdx.x, lane = tid & 31, w = tid >> 5;
    int g = lane >> 2, tg = lane & 3;

    for (int idx = tid; idx < 4096; idx += 512) Bp[idx] = g_bpack[idx];
    if (tid < DIM) bs[tid] = bias[tid];

    const float* xw = x + ((size_t)blockIdx.x * MCTA + w * 16) * DIM;

    float2 P[2][4];
#define FETCH(B, S) { int kk = (S) * 16 + 2 * tg;                    \
    P[B][0] = *(const float2*)(xw + (g    ) * DIM + kk);             \
    P[B][1] = *(const float2*)(xw + (g + 8) * DIM + kk);             \
    P[B][2] = *(const float2*)(xw + (g    ) * DIM + kk + 8);         \
    P[B][3] = *(const float2*)(xw + (g + 8) * DIM + kk + 8); }

    FETCH(0, 0);
    FETCH(1, 1);
    __syncthreads();   // B-pack + bias ready

    float acc[16][4];
    #pragma unroll
    for (int t = 0; t < 16; ++t)
        #pragma unroll
        for (int q = 0; q < 4; ++q) acc[t][q] = 0.f;

    #pragma unroll
    for (int s = 0; s < 8; ++s) {
        int b = s & 1;
        unsigned ah[4];
        ah[0] = pkh2(P[b][0].x, P[b][0].y);
        ah[1] = pkh2(P[b][1].x, P[b][1].y);
        ah[2] = pkh2(P[b][2].x, P[b][2].y);
        ah[3] = pkh2(P[b][3].x, P[b][3].y);
        // identity: add exact fp32 x into the matching C fragments
        acc[2*s][0]     += P[b][0].x;  acc[2*s][1]     += P[b][0].y;
        acc[2*s][2]     += P[b][1].x;  acc[2*s][3]     += P[b][1].y;
        acc[2*s + 1][0] += P[b][2].x;  acc[2*s + 1][1] += P[b][2].y;
        acc[2*s + 1][2] += P[b][3].x;  acc[2*s + 1][3] += P[b][3].y;
        if (s < 6) FETCH(b, s + 2);
        const uint2* Bq = Bp + s * 512 + lane;
        #pragma unroll
        for (int t = 0; t < 16; ++t) {
            uint2 bb = Bq[t * 32];
            mma16816h(acc[t], ah, bb.x, bb.y);   // x_h16 * E_16
        }
    }
#undef FETCH

    float* outw = out + ((size_t)blockIdx.x * MCTA + w * 16) * DIM;
    #pragma unroll
    for (int t = 0; t < 16; ++t) {
        int col = t * 8 + tg * 2;
        float b0 = bs[col], b1 = bs[col + 1];
        *(float2*)(outw + (g    ) * DIM + col) = make_float2(acc[t][0] + b0, acc[t][1] + b1);
        *(float2*)(outw + (g + 8) * DIM + col) = make_float2(acc[t][2] + b0, acc[t][3] + b1);
    }
}

// ---------------- launcher ----------------
extern "C" void kernel_launch(void* const* d_in, const int* in_sizes, int n_in,
                              void* d_out, int out_size) {
    const float* x      = (const float*)d_in[0];
    const float* angles = (const float*)d_in[1];
    const float* bias   = (const float*)d_in[2];
    float* out = (float*)d_out;

    const int PART_SMEM  = DIM * DIM * 4;              // 65536 dynamic
    const int CHAIN_SMEM = (16384 + 2048) * 4;         // 73728
    const int GEMM_SMEM  = 4096 * 8 + DIM * 4;         // 33280

    cudaFuncSetAttribute(partials_kernel, cudaFuncAttributeMaxDynamicSharedMemorySize, PART_SMEM);
    cudaFuncSetAttribute(chain_kernel,    cudaFuncAttributeMaxDynamicSharedMemorySize, CHAIN_SMEM);
    cudaFuncSetAttribute(gemm_kernel,     cudaFuncAttributeMaxDynamicSharedMemorySize, GEMM_SMEM);

    partials_kernel<<<NG, 128, PART_SMEM>>>(angles);
    chain_kernel<<<16, 256, CHAIN_SMEM>>>();
    gemm_kernel<<<MTILES, 512, GEMM_SMEM>>>(x, bias, out);
}

// round 7
// speedup vs baseline: 1.2101x; 1.0251x over previous
#include <cuda_runtime.h>
#include <cuda_bf16.h>
#include <cuda_fp16.h>
#include <cstdint>

#define DIM   128
#define NP    8128
#define BATCH 262144
#define NG    8
#define GROUP (NP / NG)          // 1016
#define MCTA  128
#define MTILES (BATCH / MCTA)    // 2048

// ---------------- scratch (no cudaMalloc allowed) ----------------
__device__ float  g_parts[NG * DIM * DIM];   // column-major partial products
__device__ uint2  g_bpack[8 * 16 * 32];      // [kstep][ntile][lane] -> fp16 {E0,E1}

// ---------------- helpers ----------------
__device__ __forceinline__ unsigned pkh2(float a, float b) {
    __half2 t = __floats2half2_rn(a, b);     // .x = a (low half)
    return *reinterpret_cast<unsigned*>(&t);
}

__device__ __forceinline__ void mma16816h(float* c, const unsigned* a, unsigned b0, unsigned b1) {
    asm("mma.sync.aligned.m16n8k16.row.col.f32.f16.f16.f32 "
        "{%0,%1,%2,%3}, {%4,%5,%6,%7}, {%8,%9}, {%0,%1,%2,%3};\n"
        : "+f"(c[0]), "+f"(c[1]), "+f"(c[2]), "+f"(c[3])
        : "r"(a[0]), "r"(a[1]), "r"(a[2]), "r"(a[3]), "r"(b0), "r"(b1));
}

// ---------------- phase 1a: 8 partial products, chunked static-prefetch chain ----------------
// ws padded to DIM+8 columns; cs padded by 8 -> prefetch beyond row end is memory-safe
// (garbage values are never consumed: the scalar tail re-reads smem).
__global__ __launch_bounds__(128) void partials_kernel(const float* __restrict__ angles) {
    __shared__ float2 cs[GROUP + 8];
    extern __shared__ float ws[];   // column-major ws[c*DIM + r], (DIM+8)*DIM floats
    int r = threadIdx.x, gI = blockIdx.x;

    for (int p = r; p < GROUP; p += 128) {
        float s, c;
        sincosf(angles[gI * GROUP + p], &s, &c);
        cs[p] = make_float2(c, s);
    }
    for (int c = 0; c < DIM; ++c) ws[c * DIM + r] = (c == r) ? 1.f : 0.f;
    __syncthreads();

    // locate start pair (i, j0) for this group
    int p0 = gI * GROUP;
    int i = 0, rem = p0;
    while (rem >= DIM - 1 - i) { rem -= DIM - 1 - i; ++i; }
    int j0 = i + 1 + rem;

    int p = 0;
    while (p < GROUP) {
        float wi = ws[i * DIM + r];
        int navail = GROUP - p;
        int jend = DIM;
        if (jend - j0 > navail) jend = j0 + navail;
        int j = j0;

        if (jend - j >= 8) {
            float  f[8];
            float2 v[8];
            #pragma unroll
            for (int q = 0; q < 8; ++q) { f[q] = ws[(j + q) * DIM + r]; v[q] = cs[p + q]; }
            while (j + 8 <= jend) {
                #pragma unroll
                for (int q = 0; q < 8; ++q) {
                    float wj = f[q]; float2 vv = v[q];
                    float nwj = fmaf(wj, vv.x, -(wi * vv.y));
                    wi = fmaf(wi, vv.x, wj * vv.y);
                    ws[(j + q) * DIM + r] = nwj;
                    f[q] = ws[(j + q + 8) * DIM + r];   // padded-safe prefetch
                    v[q] = cs[p + q + 8];               // padded-safe prefetch
                }
                j += 8; p += 8;
            }
        }
        for (; j < jend; ++j, ++p) {
            float2 vv = cs[p];
            float wj = ws[j * DIM + r];
            float nwj = fmaf(wj, vv.x, -(wi * vv.y));
            wi = fmaf(wi, vv.x, wj * vv.y);
            ws[j * DIM + r] = nwj;
        }
        ws[i * DIM + r] = wi;
        ++i; j0 = i + 1;
    }
    __syncthreads();
    for (int idx = r; idx < DIM * DIM; idx += 128)
        g_parts[gI * DIM * DIM + idx] = ws[idx];
}

// ---------------- phase 1b: W cols via right-to-left chain; emit E = W - I (fp16) ----------------
__global__ __launch_bounds__(256) void chain_kernel() {
    extern __shared__ float sm2[];
    float* P  = sm2;            // 16384 floats (full P_m)
    float* Sa = sm2 + 16384;    // 1024
    float* Sb = Sa + 1024;      // 1024

    int tid = threadIdx.x, r = tid & 127, h = tid >> 7;  // h in {0,1}
    int c0 = blockIdx.x * 8;

    for (int i = tid; i < 1024; i += 256)
        Sa[i] = g_parts[7 * DIM * DIM + c0 * DIM + i];

    float* S = Sa; float* S2 = Sb;
    for (int m = 6; m >= 0; --m) {
        float4* P4 = (float4*)P;
        const float4* G4 = (const float4*)(g_parts + m * DIM * DIM);
        #pragma unroll 4
        for (int i = tid; i < 4096; i += 256) P4[i] = G4[i];
        __syncthreads();

        float acc[4] = {0.f, 0.f, 0.f, 0.f};
        #pragma unroll 4
        for (int k = 0; k < DIM; k += 4) {
            float p0 = P[(k + 0) * DIM + r];
            float p1 = P[(k + 1) * DIM + r];
            float p2 = P[(k + 2) * DIM + r];
            float p3 = P[(k + 3) * DIM + r];
            #pragma unroll
            for (int cc = 0; cc < 4; ++cc) {
                float4 s4 = *(const float4*)&S[(h * 4 + cc) * DIM + k];
                acc[cc] = fmaf(p0, s4.x, acc[cc]);
                acc[cc] = fmaf(p1, s4.y, acc[cc]);
                acc[cc] = fmaf(p2, s4.z, acc[cc]);
                acc[cc] = fmaf(p3, s4.w, acc[cc]);
            }
        }
        __syncthreads();
        #pragma unroll
        for (int cc = 0; cc < 4; ++cc)
            S2[(h * 4 + cc) * DIM + r] = acc[cc];
        __syncthreads();
        float* tmp = S; S = S2; S2 = tmp;
    }

    // pack fp16 E-fragments: 256 threads = 8 ksteps x 32 lanes
    {
        int lane = tid & 31, s = tid >> 5;
        int g2 = lane >> 2, tg2 = lane & 3;
        int k0 = s * 16 + tg2 * 2;
        int n  = c0 + g2;
        const float* Wc = S + g2 * DIM;
        float w00 = Wc[k0]     - ((k0     == n) ? 1.f : 0.f);
        float w01 = Wc[k0 + 1] - ((k0 + 1 == n) ? 1.f : 0.f);
        float w10 = Wc[k0 + 8] - ((k0 + 8 == n) ? 1.f : 0.f);
        float w11 = Wc[k0 + 9] - ((k0 + 9 == n) ? 1.f : 0.f);
        uint2 bp;
        bp.x = pkh2(w00, w01);
        bp.y = pkh2(w10, w11);
        g_bpack[s * 512 + blockIdx.x * 32 + lane] = bp;
    }
}

// ---------------- phase 2: GEMM  out = x + x_h16 @ E_16 + bias ----------------
// 256 threads/CTA (8 warps x 16 rows = 128-row tile), 2 CTAs/SM so one CTA's
// DRAM phases overlap the other's mma phase. A gmem->regs, depth-2 prefetch.
__global__ __launch_bounds__(256, 2) void gemm_kernel(const float* __restrict__ x,
                                                      const float* __restrict__ bias,
                                                      float* __restrict__ out) {
    extern __shared__ char smraw[];
    uint2* Bp = (uint2*)smraw;               // 4096 uint2 = 32KB
    float* bs = (float*)(Bp + 4096);         // 128 floats

    int tid = threadIdx.x, lane = tid & 31, w = tid >> 5;
    int g = lane >> 2, tg = lane & 3;

    for (int idx = tid; idx < 4096; idx += 256) Bp[idx] = g_bpack[idx];
    if (tid < DIM) bs[tid] = bias[tid];

    const float* xw = x + ((size_t)blockIdx.x * MCTA + w * 16) * DIM;

    float2 P[2][4];
#define FETCH(B, S) { int kk = (S) * 16 + 2 * tg;                    \
    P[B][0] = *(const float2*)(xw + (g    ) * DIM + kk);             \
    P[B][1] = *(const float2*)(xw + (g + 8) * DIM + kk);             \
    P[B][2] = *(const float2*)(xw + (g    ) * DIM + kk + 8);         \
    P[B][3] = *(const float2*)(xw + (g + 8) * DIM + kk + 8); }

    FETCH(0, 0);
    FETCH(1, 1);
    __syncthreads();   // B-pack + bias ready

    float acc[16][4];
    #pragma unroll
    for (int t = 0; t < 16; ++t)
        #pragma unroll
        for (int q = 0; q < 4; ++q) acc[t][q] = 0.f;

    #pragma unroll
    for (int s = 0; s < 8; ++s) {
        int b = s & 1;
        unsigned ah[4];
        ah[0] = pkh2(P[b][0].x, P[b][0].y);
        ah[1] = pkh2(P[b][1].x, P[b][1].y);
        ah[2] = pkh2(P[b][2].x, P[b][2].y);
        ah[3] = pkh2(P[b][3].x, P[b][3].y);
        // identity: add exact fp32 x into the matching C fragments
        acc[2*s][0]     += P[b][0].x;  acc[2*s][1]     += P[b][0].y;
        acc[2*s][2]     += P[b][1].x;  acc[2*s][3]     += P[b][1].y;
        acc[2*s + 1][0] += P[b][2].x;  acc[2*s + 1][1] += P[b][2].y;
        acc[2*s + 1][2] += P[b][3].x;  acc[2*s + 1][3] += P[b][3].y;
        if (s < 6) FETCH(b, s + 2);
        const uint2* Bq = Bp + s * 512 + lane;
        #pragma unroll
        for (int t = 0; t < 16; ++t) {
            uint2 bb = Bq[t * 32];
            mma16816h(acc[t], ah, bb.x, bb.y);   // x_h16 * E_16
        }
    }
#undef FETCH

    float* outw = out + ((size_t)blockIdx.x * MCTA + w * 16) * DIM;
    #pragma unroll
    for (int t = 0; t < 16; ++t) {
        int col = t * 8 + tg * 2;
        float b0 = bs[col], b1 = bs[col + 1];
        *(float2*)(outw + (g    ) * DIM + col) = make_float2(acc[t][0] + b0, acc[t][1] + b1);
        *(float2*)(outw + (g + 8) * DIM + col) = make_float2(acc[t][2] + b0, acc[t][3] + b1);
    }
}

// ---------------- launcher ----------------
extern "C" void kernel_launch(void* const* d_in, const int* in_sizes, int n_in,
                              void* d_out, int out_size) {
    const float* x      = (const float*)d_in[0];
    const float* angles = (const float*)d_in[1];
    const float* bias   = (const float*)d_in[2];
    float* out = (float*)d_out;

    const int PART_SMEM  = (DIM + 8) * DIM * 4;        // 69632 dynamic (padded)
    const int CHAIN_SMEM = (16384 + 2048) * 4;         // 73728
    const int GEMM_SMEM  = 4096 * 8 + DIM * 4;         // 33280

    cudaFuncSetAttribute(partials_kernel, cudaFuncAttributeMaxDynamicSharedMemorySize, PART_SMEM);
    cudaFuncSetAttribute(chain_kernel,    cudaFuncAttributeMaxDynamicSharedMemorySize, CHAIN_SMEM);
    cudaFuncSetAttribute(gemm_kernel,     cudaFuncAttributeMaxDynamicSharedMemorySize, GEMM_SMEM);

    partials_kernel<<<NG, 128, PART_SMEM>>>(angles);
    chain_kernel<<<16, 256, CHAIN_SMEM>>>();
    gemm_kernel<<<MTILES, 256, GEMM_SMEM>>>(x, bias, out);
}